// round 2
// baseline (speedup 1.0000x reference)
#include <cuda_runtime.h>
#include <stdint.h>
#include <math.h>

#define D   4096
#define RK  1024
#define BM  128
#define BK  16
#define NTOT (1u << 24)   // 4^12 probability entries

// Scratch (allocation-free rule: __device__ globals). ~256 MB total.
__device__ float gA_re[NTOT];
__device__ float gA_im[NTOT];
__device__ float gB_re[NTOT];
__device__ float gB_im[NTOT];
__device__ float g_inv_trace;

// ---------------------------------------------------------------------------
// rho = U U^H. PLANE 0: re = Ar·Ac + Br·Bc (symmetric)
//              PLANE 1: im = Br·Ac - Ar·Bc (antisymmetric)
// Triangular tile grid (bi >= bj); mirror-write the transposed tile except on
// the diagonal blocks (avoids a write race that would break determinism).
// ---------------------------------------------------------------------------
template<int PLANE>
__global__ void __launch_bounds__(256) rho_gemm(const float* __restrict__ Ur,
                                                const float* __restrict__ Ui)
{
    float* __restrict__ C = PLANE ? gA_im : gA_re;

    int l = blockIdx.x;
    int bi = (int)((sqrtf(8.0f * (float)l + 1.0f) - 1.0f) * 0.5f);
    while ((bi + 1) * (bi + 2) / 2 <= l) bi++;
    while (bi * (bi + 1) / 2 > l) bi--;
    int bj = l - bi * (bi + 1) / 2;
    int row0 = bi * BM, col0 = bj * BM;

    __shared__ float sRa[BK][BM];
    __shared__ float sRb[BK][BM];
    __shared__ float sCa[BK][BM];
    __shared__ float sCb[BK][BM];

    float acc[8][8];
#pragma unroll
    for (int i = 0; i < 8; i++)
#pragma unroll
        for (int j = 0; j < 8; j++) acc[i][j] = 0.f;

    int tid = threadIdx.x;
    int tx = tid & 15, ty = tid >> 4;

    for (int k0 = 0; k0 < RK; k0 += BK) {
#pragma unroll
        for (int u = 0; u < 2; u++) {
            int l4 = tid + u * 256;        // 0..511 float4 slots
            int m  = l4 >> 2;              // 0..127 (tile row)
            int k4 = (l4 & 3) << 2;        // 0,4,8,12
            float4 va = *(const float4*)&Ur[(size_t)(row0 + m) * RK + k0 + k4];
            float4 vb = *(const float4*)&Ui[(size_t)(row0 + m) * RK + k0 + k4];
            float4 wa = *(const float4*)&Ur[(size_t)(col0 + m) * RK + k0 + k4];
            float4 wb = *(const float4*)&Ui[(size_t)(col0 + m) * RK + k0 + k4];
            sRa[k4+0][m]=va.x; sRa[k4+1][m]=va.y; sRa[k4+2][m]=va.z; sRa[k4+3][m]=va.w;
            sRb[k4+0][m]=vb.x; sRb[k4+1][m]=vb.y; sRb[k4+2][m]=vb.z; sRb[k4+3][m]=vb.w;
            sCa[k4+0][m]=wa.x; sCa[k4+1][m]=wa.y; sCa[k4+2][m]=wa.z; sCa[k4+3][m]=wa.w;
            sCb[k4+0][m]=wb.x; sCb[k4+1][m]=wb.y; sCb[k4+2][m]=wb.z; sCb[k4+3][m]=wb.w;
        }
        __syncthreads();
#pragma unroll
        for (int kk = 0; kk < BK; kk++) {
            float ra[8], rb[8], ca[8], cb[8];
#pragma unroll
            for (int i = 0; i < 8; i++) {
                ra[i] = sRa[kk][ty * 8 + i];
                rb[i] = sRb[kk][ty * 8 + i];
                ca[i] = sCa[kk][tx * 8 + i];
                cb[i] = sCb[kk][tx * 8 + i];
            }
#pragma unroll
            for (int i = 0; i < 8; i++)
#pragma unroll
                for (int j = 0; j < 8; j++) {
                    if (PLANE == 0)
                        acc[i][j] += ra[i] * ca[j] + rb[i] * cb[j];
                    else
                        acc[i][j] += rb[i] * ca[j] - ra[i] * cb[j];
                }
        }
        __syncthreads();
    }

#pragma unroll
    for (int i = 0; i < 8; i++) {
        int r = row0 + ty * 8 + i;
#pragma unroll
        for (int j = 0; j < 8; j++) {
            int c = col0 + tx * 8 + j;
            C[(size_t)r * D + c] = acc[i][j];
        }
    }
    if (bi != bj) {
#pragma unroll
        for (int i = 0; i < 8; i++) {
            int r = row0 + ty * 8 + i;
#pragma unroll
            for (int j = 0; j < 8; j++) {
                int c = col0 + tx * 8 + j;
                C[(size_t)c * D + r] = PLANE ? -acc[i][j] : acc[i][j];
            }
        }
    }
}

// ---------------------------------------------------------------------------
// trace: sum of re diagonal of rho -> 1/trace
// ---------------------------------------------------------------------------
__global__ void trace_kernel()
{
    __shared__ float red[256];
    float s = 0.f;
    for (int i = threadIdx.x; i < D; i += 256)
        s += gA_re[(size_t)i * D + i];
    red[threadIdx.x] = s;
    __syncthreads();
    for (int w = 128; w; w >>= 1) {
        if (threadIdx.x < w) red[threadIdx.x] += red[threadIdx.x + w];
        __syncthreads();
    }
    if (threadIdx.x == 0) g_inv_trace = 1.0f / red[0];
}

// ---------------------------------------------------------------------------
// One fused 2-qubit partial-trace sweep:
//   out[(k,S), a, t] = sum_{I,J in [0,4)} Mm[S][J][I] * in[k, J*rp + a, I*cp + t]
// with Mm[(s1,s2)][(j1,j2)][(i1,i2)] = M[s1,i1,j1] * M[s2,i2,j2] (complex).
// Input shape [k, 4*rp, 4*cp]; rp == cp == 2^lc. 2^20 threads total.
// dir = 0: A -> B, dir = 1: B -> A.
// ---------------------------------------------------------------------------
__global__ void __launch_bounds__(256) qmt_sweep(int dir,
                                                 const float* __restrict__ Mr,
                                                 const float* __restrict__ Mi,
                                                 int lc)
{
    const float* __restrict__ in_re = dir ? gB_re : gA_re;
    const float* __restrict__ in_im = dir ? gB_im : gA_im;
    float* __restrict__ o_re = dir ? gA_re : gB_re;
    float* __restrict__ o_im = dir ? gA_im : gB_im;

    __shared__ float sMr[256];
    __shared__ float sMi[256];
    int tid = threadIdx.x;
    {
        int S = tid >> 4, rem = tid & 15;
        int J = rem >> 2, I = rem & 3;
        int s1 = S >> 2, s2 = S & 3;
        int j1 = J >> 1, j2 = J & 1;
        int i1 = I >> 1, i2 = I & 1;
        float ar = Mr[s1 * 4 + i1 * 2 + j1], ai = Mi[s1 * 4 + i1 * 2 + j1];
        float br = Mr[s2 * 4 + i2 * 2 + j2], bi = Mi[s2 * 4 + i2 * 2 + j2];
        sMr[tid] = ar * br - ai * bi;
        sMi[tid] = ar * bi + ai * br;
    }
    __syncthreads();

    unsigned gid = blockIdx.x * 256u + (unsigned)tid;   // 0 .. 2^20-1
    unsigned cp = 1u << lc;
    unsigned t = gid & (cp - 1u);
    unsigned a = (gid >> lc) & (cp - 1u);
    unsigned k = gid >> (2 * lc);
    unsigned base_in = k << (2 * lc + 4);               // k * 16*rp*cp

    float xr[16], xi[16];
#pragma unroll
    for (int J = 0; J < 4; J++)
#pragma unroll
        for (int I = 0; I < 4; I++) {
            unsigned off = base_in
                         + ((((unsigned)J << lc) + a) << (lc + 2))
                         + ((unsigned)I << lc) + t;
            xr[J * 4 + I] = in_re[off];
            xi[J * 4 + I] = in_im[off];
        }

#pragma unroll
    for (int S = 0; S < 16; S++) {
        float aR = 0.f, aI = 0.f;
#pragma unroll
        for (int q = 0; q < 16; q++) {
            float mr = sMr[S * 16 + q], mi = sMi[S * 16 + q];
            aR = fmaf(mr, xr[q], aR);
            aR = fmaf(-mi, xi[q], aR);
            aI = fmaf(mr, xi[q], aI);
            aI = fmaf(mi, xr[q], aI);
        }
        unsigned off = (((k << 4) + (unsigned)S) << (2 * lc)) + (a << lc) + t;
        o_re[off] = aR;
        o_im[off] = aI;
    }
}

// ---------------------------------------------------------------------------
// Gather: out[i] = P_all[idx[i]] / trace  (only the real plane matters)
// P_idxs is int32 on the wire (JAX x64 disabled downcasts the requested int64).
// Mask with NTOT-1 so even a bad index can never fault (wrong values would
// surface as rel_err, which is debuggable; an illegal access is not).
// ---------------------------------------------------------------------------
__global__ void gather_kernel(const int* __restrict__ idx,
                              float* __restrict__ out, int n)
{
    int i = blockIdx.x * 256 + threadIdx.x;
    if (i < n) out[i] = gA_re[(unsigned)idx[i] & (NTOT - 1u)] * g_inv_trace;
}

// ---------------------------------------------------------------------------
extern "C" void kernel_launch(void* const* d_in, const int* in_sizes, int n_in,
                              void* d_out, int out_size)
{
    const float* params = (const float*)d_in[0];      // (2, 4096, 1024)
    const float* Mr = (const float*)d_in[1];          // (4,2,2)
    const float* Mi = (const float*)d_in[2];          // (4,2,2)
    const int* idx = (const int*)d_in[3];             // (1e6,) int32 (x64 off)
    float* out = (float*)d_out;

    const float* Ur = params;
    const float* Ui = params + (size_t)D * RK;

    const int ntiles = D / BM;                 // 32
    const int tri = ntiles * (ntiles + 1) / 2; // 528

    rho_gemm<0><<<tri, 256>>>(Ur, Ui);
    rho_gemm<1><<<tri, 256>>>(Ur, Ui);
    trace_kernel<<<1, 256>>>();

    int dir = 0;                               // rho lives in A
    for (int n = 1; n <= 6; n++) {
        qmt_sweep<<<4096, 256>>>(dir, Mr, Mi, 12 - 2 * n);
        dir ^= 1;
    }
    // 6 sweeps: A->B->A->B->A->B->A, final result in gA_re.

    int nq = in_sizes[3];
    gather_kernel<<<(nq + 255) / 256, 256>>>(idx, out, nq);
}

// round 4
// speedup vs baseline: 2.2874x; 2.2874x over previous
#include <cuda_runtime.h>
#include <stdint.h>
#include <math.h>

#define D    4096
#define RK   1024
#define NTOT (1u << 24)     // 4^12 probability entries
#define PIT  36             // smem pitch in floats (conflict-free frag loads)

// ---------------------------------------------------------------------------
// Scratch (__device__ globals per allocation rules). 256MB ping-pong.
// ---------------------------------------------------------------------------
__device__ float gA_re[NTOT];
__device__ float gA_im[NTOT];
__device__ float gB_re[NTOT];
__device__ float gB_im[NTOT];
__device__ float g_inv_trace;

// ---------------------------------------------------------------------------
// helpers
// ---------------------------------------------------------------------------
static __device__ __forceinline__ uint32_t f2tf(float x) {
    uint32_t r; asm("cvt.rna.tf32.f32 %0, %1;" : "=r"(r) : "f"(x)); return r;
}
static __device__ __forceinline__ float u2f(uint32_t x) { return __uint_as_float(x); }

static __device__ __forceinline__ void mma8(float c[4], const uint32_t a[4],
                                            const uint32_t b[2]) {
    asm volatile(
        "mma.sync.aligned.m16n8k8.row.col.f32.tf32.tf32.f32 "
        "{%0,%1,%2,%3}, {%4,%5,%6,%7}, {%8,%9}, {%0,%1,%2,%3};\n"
        : "+f"(c[0]), "+f"(c[1]), "+f"(c[2]), "+f"(c[3])
        : "r"(a[0]), "r"(a[1]), "r"(a[2]), "r"(a[3]), "r"(b[0]), "r"(b[1]));
}

// ---------------------------------------------------------------------------
// rho = U U^H via 3xTF32 mma.sync GEMM (legacy tensor path, sm_103-safe).
// Tile 128x128, triangular grid (528 CTAs, bi>=bj), K-chunk 32, double-buffered
// cp.async. 8 warps as 2(m) x 4(n), warp tile 64x32, m16n8k8 fragments.
// re = ArBr^T + AiBi^T ; im = AiBr^T - ArBi^T (minus via sign-flipped Ar frags).
// ---------------------------------------------------------------------------
__global__ void __launch_bounds__(256, 1) gemm_mma(const float* __restrict__ Ur,
                                                   const float* __restrict__ Ui)
{
    extern __shared__ float sm[];   // 2 buffers * 4 planes * 128*PIT floats

    const int tid  = threadIdx.x;
    const int lane = tid & 31;
    const int wid  = tid >> 5;
    const int gid  = lane >> 2;     // 0..7
    const int tig  = lane & 3;      // 0..3
    const int wm   = wid >> 2;      // 0..1
    const int wn   = wid & 3;       // 0..3

    // triangular tile index
    int l = blockIdx.x;
    int bi = (int)((sqrtf(8.0f * (float)l + 1.0f) - 1.0f) * 0.5f);
    while ((bi + 1) * (bi + 2) / 2 <= l) bi++;
    while (bi * (bi + 1) / 2 > l) bi--;
    int bj = l - bi * (bi + 1) / 2;
    const int row0 = bi * 128, col0 = bj * 128;

    const int PLN = 128 * PIT;      // floats per plane
    const int BUF = 4 * PLN;        // floats per stage buffer

    // ---- async loader for one K-chunk (32 k) into buffer `buf` ----
    auto load_chunk = [&](int buf, int k0) {
        float* base = sm + buf * BUF;
#pragma unroll
        for (int u = 0; u < 16; u++) {
            int i = tid + u * 256;              // 0..4095 float4 slots
            int plane = i >> 10;                // 0 Ar, 1 Ai, 2 Br, 3 Bi
            int rem = i & 1023;
            int r = rem >> 3, c4 = (rem & 7) << 2;
            const float* g = (plane & 1) ? Ui : Ur;
            int baser = (plane < 2) ? row0 : col0;
            const float* src = g + (size_t)(baser + r) * RK + k0 + c4;
            uint32_t dst = (uint32_t)__cvta_generic_to_shared(
                base + plane * PLN + r * PIT + c4);
            asm volatile("cp.async.cg.shared.global [%0], [%1], 16;"
                         :: "r"(dst), "l"(src));
        }
    };

    float accre[4][4][4], accim[4][4][4];
#pragma unroll
    for (int a = 0; a < 4; a++)
#pragma unroll
        for (int b = 0; b < 4; b++)
#pragma unroll
            for (int q = 0; q < 4; q++) { accre[a][b][q] = 0.f; accim[a][b][q] = 0.f; }

    load_chunk(0, 0);
    asm volatile("cp.async.commit_group;");

#pragma unroll 1
    for (int c = 0; c < 32; c++) {
        if (c + 1 < 32) load_chunk((c + 1) & 1, (c + 1) * 32);
        asm volatile("cp.async.commit_group;");
        asm volatile("cp.async.wait_group 1;");
        __syncthreads();

        const float* bb  = sm + (c & 1) * BUF;
        const float* sAr = bb;
        const float* sAi = bb + PLN;
        const float* sBr = bb + 2 * PLN;
        const float* sBi = bb + 3 * PLN;

#pragma unroll
        for (int kk = 0; kk < 4; kk++) {
            const int kb = kk * 8 + tig;

            uint32_t Brh[4][2], Brl[4][2], Bih[4][2], Bil[4][2];
#pragma unroll
            for (int nf = 0; nf < 4; nf++) {
                int n = (wn * 32 + nf * 8 + gid) * PIT;
                float r0 = sBr[n + kb],     r1 = sBr[n + kb + 4];
                float i0 = sBi[n + kb],     i1 = sBi[n + kb + 4];
                Brh[nf][0] = f2tf(r0); Brl[nf][0] = f2tf(r0 - u2f(Brh[nf][0]));
                Brh[nf][1] = f2tf(r1); Brl[nf][1] = f2tf(r1 - u2f(Brh[nf][1]));
                Bih[nf][0] = f2tf(i0); Bil[nf][0] = f2tf(i0 - u2f(Bih[nf][0]));
                Bih[nf][1] = f2tf(i1); Bil[nf][1] = f2tf(i1 - u2f(Bih[nf][1]));
            }

            uint32_t Ah[4][4], Al[4][4];
            // ---- plane Ar ----
#pragma unroll
            for (int mf = 0; mf < 4; mf++) {
                int r = (wm * 64 + mf * 16 + gid) * PIT;
                float x0 = sAr[r + kb];
                float x1 = sAr[r + 8 * PIT + kb];
                float x2 = sAr[r + kb + 4];
                float x3 = sAr[r + 8 * PIT + kb + 4];
                Ah[mf][0] = f2tf(x0); Al[mf][0] = f2tf(x0 - u2f(Ah[mf][0]));
                Ah[mf][1] = f2tf(x1); Al[mf][1] = f2tf(x1 - u2f(Ah[mf][1]));
                Ah[mf][2] = f2tf(x2); Al[mf][2] = f2tf(x2 - u2f(Ah[mf][2]));
                Ah[mf][3] = f2tf(x3); Al[mf][3] = f2tf(x3 - u2f(Ah[mf][3]));
            }
            // re += Ar * Br   (hh, hl, lh)
#pragma unroll
            for (int mf = 0; mf < 4; mf++)
#pragma unroll
                for (int nf = 0; nf < 4; nf++) {
                    mma8(accre[mf][nf], Ah[mf], Brh[nf]);
                    mma8(accre[mf][nf], Ah[mf], Brl[nf]);
                    mma8(accre[mf][nf], Al[mf], Brh[nf]);
                }
            // negate Ar fragments (exact sign flip)
#pragma unroll
            for (int mf = 0; mf < 4; mf++)
#pragma unroll
                for (int q = 0; q < 4; q++) {
                    Ah[mf][q] ^= 0x80000000u;
                    Al[mf][q] ^= 0x80000000u;
                }
            // im += (-Ar) * Bi
#pragma unroll
            for (int mf = 0; mf < 4; mf++)
#pragma unroll
                for (int nf = 0; nf < 4; nf++) {
                    mma8(accim[mf][nf], Ah[mf], Bih[nf]);
                    mma8(accim[mf][nf], Ah[mf], Bil[nf]);
                    mma8(accim[mf][nf], Al[mf], Bih[nf]);
                }
            // ---- plane Ai ----
#pragma unroll
            for (int mf = 0; mf < 4; mf++) {
                int r = (wm * 64 + mf * 16 + gid) * PIT;
                float x0 = sAi[r + kb];
                float x1 = sAi[r + 8 * PIT + kb];
                float x2 = sAi[r + kb + 4];
                float x3 = sAi[r + 8 * PIT + kb + 4];
                Ah[mf][0] = f2tf(x0); Al[mf][0] = f2tf(x0 - u2f(Ah[mf][0]));
                Ah[mf][1] = f2tf(x1); Al[mf][1] = f2tf(x1 - u2f(Ah[mf][1]));
                Ah[mf][2] = f2tf(x2); Al[mf][2] = f2tf(x2 - u2f(Ah[mf][2]));
                Ah[mf][3] = f2tf(x3); Al[mf][3] = f2tf(x3 - u2f(Ah[mf][3]));
            }
            // re += Ai * Bi
#pragma unroll
            for (int mf = 0; mf < 4; mf++)
#pragma unroll
                for (int nf = 0; nf < 4; nf++) {
                    mma8(accre[mf][nf], Ah[mf], Bih[nf]);
                    mma8(accre[mf][nf], Ah[mf], Bil[nf]);
                    mma8(accre[mf][nf], Al[mf], Bih[nf]);
                }
            // im += Ai * Br
#pragma unroll
            for (int mf = 0; mf < 4; mf++)
#pragma unroll
                for (int nf = 0; nf < 4; nf++) {
                    mma8(accim[mf][nf], Ah[mf], Brh[nf]);
                    mma8(accim[mf][nf], Ah[mf], Brl[nf]);
                    mma8(accim[mf][nf], Al[mf], Brh[nf]);
                }
        }
        __syncthreads();
    }

    // ---- epilogue: write tile + mirror (skip mirror on diagonal tiles) ----
#pragma unroll
    for (int mf = 0; mf < 4; mf++)
#pragma unroll
        for (int nf = 0; nf < 4; nf++) {
            unsigned r = row0 + wm * 64 + mf * 16 + gid;
            unsigned cc = col0 + wn * 32 + nf * 8 + 2 * tig;
            const float* cr = accre[mf][nf];
            const float* ci = accim[mf][nf];
            gA_re[(size_t)r * D + cc]           = cr[0];
            gA_re[(size_t)r * D + cc + 1]       = cr[1];
            gA_re[(size_t)(r + 8) * D + cc]     = cr[2];
            gA_re[(size_t)(r + 8) * D + cc + 1] = cr[3];
            gA_im[(size_t)r * D + cc]           = ci[0];
            gA_im[(size_t)r * D + cc + 1]       = ci[1];
            gA_im[(size_t)(r + 8) * D + cc]     = ci[2];
            gA_im[(size_t)(r + 8) * D + cc + 1] = ci[3];
            if (bi != bj) {
                gA_re[(size_t)cc * D + r]           = cr[0];
                gA_re[(size_t)(cc + 1) * D + r]     = cr[1];
                gA_re[(size_t)cc * D + r + 8]       = cr[2];
                gA_re[(size_t)(cc + 1) * D + r + 8] = cr[3];
                gA_im[(size_t)cc * D + r]           = -ci[0];
                gA_im[(size_t)(cc + 1) * D + r]     = -ci[1];
                gA_im[(size_t)cc * D + r + 8]       = -ci[2];
                gA_im[(size_t)(cc + 1) * D + r + 8] = -ci[3];
            }
        }
}

// ---------------------------------------------------------------------------
// trace: sum of re diagonal of rho -> 1/trace
// ---------------------------------------------------------------------------
__global__ void trace_kernel()
{
    __shared__ float red[256];
    float s = 0.f;
    for (int i = threadIdx.x; i < D; i += 256)
        s += gA_re[(size_t)i * D + i];
    red[threadIdx.x] = s;
    __syncthreads();
    for (int w = 128; w; w >>= 1) {
        if (threadIdx.x < w) red[threadIdx.x] += red[threadIdx.x + w];
        __syncthreads();
    }
    if (threadIdx.x == 0) g_inv_trace = 1.0f / red[0];
}

// ---------------------------------------------------------------------------
// Fused 2-qubit partial-trace sweep, factored into two 4-term complex stages
// (512 FMA/thread instead of 1024).
//   out[(k,s1,s2), a, t] = sum_{j1 i1 j2 i2} M[s1,i1,j1] M[s2,i2,j2]
//                          * in[k, (2j1+j2)*rp + a, (2i1+i2)*cp + t]
// dir=0: A->B, dir=1: B->A. wim=0 skips imag store (last sweep).
// ---------------------------------------------------------------------------
__global__ void __launch_bounds__(256) qmt_sweep(int dir,
                                                 const float* __restrict__ Mr,
                                                 const float* __restrict__ Mi,
                                                 int lc, int wim)
{
    const float* __restrict__ in_re = dir ? gB_re : gA_re;
    const float* __restrict__ in_im = dir ? gB_im : gA_im;
    float* __restrict__ o_re = dir ? gA_re : gB_re;
    float* __restrict__ o_im = dir ? gA_im : gB_im;

    __shared__ float sr[16], si[16];   // M[s,i,j] at s*4+i*2+j
    int tid = threadIdx.x;
    if (tid < 16) { sr[tid] = Mr[tid]; si[tid] = Mi[tid]; }
    __syncthreads();

    unsigned gid = blockIdx.x * 256u + (unsigned)tid;   // 0 .. 2^20-1
    unsigned cp = 1u << lc;
    unsigned t = gid & (cp - 1u);
    unsigned a = (gid >> lc) & (cp - 1u);
    unsigned k = gid >> (2 * lc);
    unsigned base_in = k << (2 * lc + 4);

    float xr[16], xi[16];
#pragma unroll
    for (int J = 0; J < 4; J++)
#pragma unroll
        for (int I = 0; I < 4; I++) {
            unsigned off = base_in
                         + ((((unsigned)J << lc) + a) << (lc + 2))
                         + ((unsigned)I << lc) + t;
            xr[J * 4 + I] = in_re[off];
            xi[J * 4 + I] = in_im[off];
        }

    // stage 1: contract (j1,i1): y[s1][(j2,i2)]
    float yr[16], yi[16];
#pragma unroll
    for (int s1 = 0; s1 < 4; s1++)
#pragma unroll
        for (int j2 = 0; j2 < 2; j2++)
#pragma unroll
            for (int i2 = 0; i2 < 2; i2++) {
                float ar = 0.f, ai = 0.f;
#pragma unroll
                for (int j1 = 0; j1 < 2; j1++)
#pragma unroll
                    for (int i1 = 0; i1 < 2; i1++) {
                        float mr = sr[s1 * 4 + i1 * 2 + j1];
                        float mi = si[s1 * 4 + i1 * 2 + j1];
                        float vr = xr[(j1 * 2 + j2) * 4 + i1 * 2 + i2];
                        float vi = xi[(j1 * 2 + j2) * 4 + i1 * 2 + i2];
                        ar = fmaf(mr, vr, ar); ar = fmaf(-mi, vi, ar);
                        ai = fmaf(mr, vi, ai); ai = fmaf(mi, vr, ai);
                    }
                yr[s1 * 4 + j2 * 2 + i2] = ar;
                yi[s1 * 4 + j2 * 2 + i2] = ai;
            }

    // stage 2: contract (j2,i2)
#pragma unroll
    for (int s1 = 0; s1 < 4; s1++)
#pragma unroll
        for (int s2 = 0; s2 < 4; s2++) {
            float aR = 0.f, aI = 0.f;
#pragma unroll
            for (int j2 = 0; j2 < 2; j2++)
#pragma unroll
                for (int i2 = 0; i2 < 2; i2++) {
                    float mr = sr[s2 * 4 + i2 * 2 + j2];
                    float mi = si[s2 * 4 + i2 * 2 + j2];
                    float vr = yr[s1 * 4 + j2 * 2 + i2];
                    float vi = yi[s1 * 4 + j2 * 2 + i2];
                    aR = fmaf(mr, vr, aR); aR = fmaf(-mi, vi, aR);
                    aI = fmaf(mr, vi, aI); aI = fmaf(mi, vr, aI);
                }
            unsigned off = (((k << 4) + (unsigned)(s1 * 4 + s2)) << (2 * lc))
                         + (a << lc) + t;
            o_re[off] = aR;
            if (wim) o_im[off] = aI;
        }
}

// ---------------------------------------------------------------------------
// Gather: out[i] = P_all[idx[i]] / trace (real plane only; int32 indices).
// ---------------------------------------------------------------------------
__global__ void gather_kernel(const int* __restrict__ idx,
                              float* __restrict__ out, int n)
{
    int i = blockIdx.x * 256 + threadIdx.x;
    if (i < n) out[i] = gA_re[(unsigned)idx[i] & (NTOT - 1u)] * g_inv_trace;
}

// ---------------------------------------------------------------------------
extern "C" void kernel_launch(void* const* d_in, const int* in_sizes, int n_in,
                              void* d_out, int out_size)
{
    const float* params = (const float*)d_in[0];      // (2, 4096, 1024)
    const float* Mr = (const float*)d_in[1];          // (4,2,2)
    const float* Mi = (const float*)d_in[2];          // (4,2,2)
    const int* idx = (const int*)d_in[3];             // (1e6,) int32
    float* out = (float*)d_out;

    const float* Ur = params;
    const float* Ui = params + (size_t)D * RK;

    const int smem_bytes = 2 * 4 * 128 * PIT * sizeof(float);  // 147456
    cudaFuncSetAttribute(gemm_mma,
                         cudaFuncAttributeMaxDynamicSharedMemorySize, smem_bytes);

    gemm_mma<<<528, 256, smem_bytes>>>(Ur, Ui);
    trace_kernel<<<1, 256>>>();

    int dir = 0;
    for (int n = 1; n <= 6; n++) {
        qmt_sweep<<<4096, 256>>>(dir, Mr, Mi, 12 - 2 * n, n < 6 ? 1 : 0);
        dir ^= 1;
    }
    // final result (real plane) in gA_re

    int nq = in_sizes[3];
    gather_kernel<<<(nq + 255) / 256, 256>>>(idx, out, nq);
}

// round 5
// speedup vs baseline: 3.4383x; 1.5031x over previous
#include <cuda_runtime.h>
#include <cuda_bf16.h>
#include <stdint.h>
#include <math.h>

#define D    4096
#define RK   1024
#define NTOT (1u << 24)     // 4^12 probability entries
#define PITB 80             // smem row pitch in BYTES (40 bf16) — conflict-free

// ---------------------------------------------------------------------------
// Scratch (__device__ globals per allocation rules).
// ---------------------------------------------------------------------------
__device__ float gA_re[NTOT];
__device__ float gA_im[NTOT];
__device__ float gB_re[NTOT];
__device__ float gB_im[NTOT];
__device__ __nv_bfloat16 gHr[(size_t)D * RK];   // hi(Ur)
__device__ __nv_bfloat16 gLr[(size_t)D * RK];   // lo(Ur)
__device__ __nv_bfloat16 gHi[(size_t)D * RK];   // hi(Ui)
__device__ __nv_bfloat16 gLi[(size_t)D * RK];   // lo(Ui)
__device__ float g_inv_trace;

// ---------------------------------------------------------------------------
static __device__ __forceinline__ void mma16(float c[4], const uint32_t a[4],
                                             const uint32_t b[2]) {
    asm volatile(
        "mma.sync.aligned.m16n8k16.row.col.f32.bf16.bf16.f32 "
        "{%0,%1,%2,%3}, {%4,%5,%6,%7}, {%8,%9}, {%0,%1,%2,%3};\n"
        : "+f"(c[0]), "+f"(c[1]), "+f"(c[2]), "+f"(c[3])
        : "r"(a[0]), "r"(a[1]), "r"(a[2]), "r"(a[3]), "r"(b[0]), "r"(b[1]));
}
static __device__ __forceinline__ uint32_t lds32(const char* base, int off) {
    return *(const uint32_t*)(base + off);
}

// ---------------------------------------------------------------------------
// Pack: hi = bf16(x), lo = bf16(x - hi) for both planes of U.
// ---------------------------------------------------------------------------
__global__ void __launch_bounds__(256) pack_split(const float* __restrict__ Ur,
                                                  const float* __restrict__ Ui)
{
    unsigned e = blockIdx.x * 256u + threadIdx.x;   // 0 .. 4M-1
    float x = Ur[e];
    __nv_bfloat16 h = __float2bfloat16_rn(x);
    gHr[e] = h;
    gLr[e] = __float2bfloat16_rn(x - __bfloat162float(h));
    float y = Ui[e];
    __nv_bfloat16 h2 = __float2bfloat16_rn(y);
    gHi[e] = h2;
    gLi[e] = __float2bfloat16_rn(y - __bfloat162float(h2));
}

// ---------------------------------------------------------------------------
// rho = U U^H via bf16x3 mma.sync (m16n8k16). Tile 128x128, triangular grid
// (528 CTAs, bi>=bj). K-chunk 32, double-buffered cp.async; 8 smem planes per
// stage: {Ar,Ai,Br,Bi} x {hi,lo}, rows pitched at 80B.
// re = ArBr^T + AiBi^T ; im = AiBr^T - ArBi^T (minus via sign-flipped Ar).
// Split products kept: hh + hl + lh (lo*lo dropped).
// ---------------------------------------------------------------------------
__global__ void __launch_bounds__(256, 1) gemm_mma()
{
    extern __shared__ char sm[];    // 2 stages * 8 planes * 128*PITB bytes

    const int tid  = threadIdx.x;
    const int lane = tid & 31;
    const int wid  = tid >> 5;
    const int gid  = lane >> 2;     // 0..7
    const int tig  = lane & 3;      // 0..3
    const int wm   = wid >> 2;      // 0..1
    const int wn   = wid & 3;       // 0..3

    // triangular tile index
    int l = blockIdx.x;
    int bi = (int)((sqrtf(8.0f * (float)l + 1.0f) - 1.0f) * 0.5f);
    while ((bi + 1) * (bi + 2) / 2 <= l) bi++;
    while (bi * (bi + 1) / 2 > l) bi--;
    int bj = l - bi * (bi + 1) / 2;
    const int row0 = bi * 128, col0 = bj * 128;

    const int PLNB = 128 * PITB;    // 10240 B per plane
    const int BUFB = 8 * PLNB;      // 81920 B per stage

    // plane order: 0 ArH, 1 ArL, 2 AiH, 3 AiL, 4 BrH, 5 BrL, 6 BiH, 7 BiL
    auto load_chunk = [&](int buf, int k0) {
        char* base = sm + buf * BUFB;
#pragma unroll
        for (int u = 0; u < 16; u++) {
            int i = tid + u * 256;          // 0..4095 16B slots
            int plane = i >> 9;             // 0..7
            int rem = i & 511;
            int r = rem >> 2;               // 0..127
            int q = rem & 3;                // 16B slot within 64B row-chunk
            const __nv_bfloat16* arr =
                (plane == 0 || plane == 4) ? gHr :
                (plane == 1 || plane == 5) ? gLr :
                (plane == 2 || plane == 6) ? gHi : gLi;
            int baser = (plane < 4) ? row0 : col0;
            const __nv_bfloat16* src =
                arr + (size_t)(baser + r) * RK + k0 + q * 8;
            uint32_t dst = (uint32_t)__cvta_generic_to_shared(
                base + plane * PLNB + r * PITB + q * 16);
            asm volatile("cp.async.cg.shared.global [%0], [%1], 16;"
                         :: "r"(dst), "l"(src));
        }
    };

    float accre[4][4][4], accim[4][4][4];
#pragma unroll
    for (int a = 0; a < 4; a++)
#pragma unroll
        for (int b = 0; b < 4; b++)
#pragma unroll
            for (int q = 0; q < 4; q++) { accre[a][b][q] = 0.f; accim[a][b][q] = 0.f; }

    load_chunk(0, 0);
    asm volatile("cp.async.commit_group;");

#pragma unroll 1
    for (int c = 0; c < 32; c++) {
        if (c + 1 < 32) load_chunk((c + 1) & 1, (c + 1) * 32);
        asm volatile("cp.async.commit_group;");
        asm volatile("cp.async.wait_group 1;");
        __syncthreads();

        const char* bb = sm + (c & 1) * BUFB;

#pragma unroll
        for (int kk = 0; kk < 2; kk++) {      // two k16 halves of the 32-chunk
            const int kbyte = kk * 32 + tig * 4;   // within-row byte offset

            // ---- B fragments: BrH, BrL, BiH, BiL (2 regs x 4 nf each) ----
            uint32_t BrH[4][2], BrL[4][2], BiH[4][2], BiL[4][2];
#pragma unroll
            for (int nf = 0; nf < 4; nf++) {
                int n = (wn * 32 + nf * 8 + gid) * PITB;
                BrH[nf][0] = lds32(bb + 4 * PLNB, n + kbyte);
                BrH[nf][1] = lds32(bb + 4 * PLNB, n + kbyte + 16);
                BrL[nf][0] = lds32(bb + 5 * PLNB, n + kbyte);
                BrL[nf][1] = lds32(bb + 5 * PLNB, n + kbyte + 16);
                BiH[nf][0] = lds32(bb + 6 * PLNB, n + kbyte);
                BiH[nf][1] = lds32(bb + 6 * PLNB, n + kbyte + 16);
                BiL[nf][0] = lds32(bb + 7 * PLNB, n + kbyte);
                BiL[nf][1] = lds32(bb + 7 * PLNB, n + kbyte + 16);
            }

            uint32_t AH[4][4], AL[4][4];
            // ---- plane Ar (hi/lo) ----
#pragma unroll
            for (int mf = 0; mf < 4; mf++) {
                int r = (wm * 64 + mf * 16 + gid) * PITB;
                AH[mf][0] = lds32(bb,        r + kbyte);
                AH[mf][1] = lds32(bb,        r + 8 * PITB + kbyte);
                AH[mf][2] = lds32(bb,        r + kbyte + 16);
                AH[mf][3] = lds32(bb,        r + 8 * PITB + kbyte + 16);
                AL[mf][0] = lds32(bb + PLNB, r + kbyte);
                AL[mf][1] = lds32(bb + PLNB, r + 8 * PITB + kbyte);
                AL[mf][2] = lds32(bb + PLNB, r + kbyte + 16);
                AL[mf][3] = lds32(bb + PLNB, r + 8 * PITB + kbyte + 16);
            }
            // re += Ar*Br (hh, hl, lh)
#pragma unroll
            for (int mf = 0; mf < 4; mf++)
#pragma unroll
                for (int nf = 0; nf < 4; nf++) {
                    mma16(accre[mf][nf], AH[mf], BrH[nf]);
                    mma16(accre[mf][nf], AH[mf], BrL[nf]);
                    mma16(accre[mf][nf], AL[mf], BrH[nf]);
                }
            // im += (-Ar)*Bi  (exact sign flip of both bf16 halves)
#pragma unroll
            for (int mf = 0; mf < 4; mf++)
#pragma unroll
                for (int q = 0; q < 4; q++) {
                    AH[mf][q] ^= 0x80008000u;
                    AL[mf][q] ^= 0x80008000u;
                }
#pragma unroll
            for (int mf = 0; mf < 4; mf++)
#pragma unroll
                for (int nf = 0; nf < 4; nf++) {
                    mma16(accim[mf][nf], AH[mf], BiH[nf]);
                    mma16(accim[mf][nf], AH[mf], BiL[nf]);
                    mma16(accim[mf][nf], AL[mf], BiH[nf]);
                }
            // ---- plane Ai (hi/lo) ----
#pragma unroll
            for (int mf = 0; mf < 4; mf++) {
                int r = (wm * 64 + mf * 16 + gid) * PITB;
                AH[mf][0] = lds32(bb + 2 * PLNB, r + kbyte);
                AH[mf][1] = lds32(bb + 2 * PLNB, r + 8 * PITB + kbyte);
                AH[mf][2] = lds32(bb + 2 * PLNB, r + kbyte + 16);
                AH[mf][3] = lds32(bb + 2 * PLNB, r + 8 * PITB + kbyte + 16);
                AL[mf][0] = lds32(bb + 3 * PLNB, r + kbyte);
                AL[mf][1] = lds32(bb + 3 * PLNB, r + 8 * PITB + kbyte);
                AL[mf][2] = lds32(bb + 3 * PLNB, r + kbyte + 16);
                AL[mf][3] = lds32(bb + 3 * PLNB, r + 8 * PITB + kbyte + 16);
            }
            // re += Ai*Bi
#pragma unroll
            for (int mf = 0; mf < 4; mf++)
#pragma unroll
                for (int nf = 0; nf < 4; nf++) {
                    mma16(accre[mf][nf], AH[mf], BiH[nf]);
                    mma16(accre[mf][nf], AH[mf], BiL[nf]);
                    mma16(accre[mf][nf], AL[mf], BiH[nf]);
                }
            // im += Ai*Br
#pragma unroll
            for (int mf = 0; mf < 4; mf++)
#pragma unroll
                for (int nf = 0; nf < 4; nf++) {
                    mma16(accim[mf][nf], AH[mf], BrH[nf]);
                    mma16(accim[mf][nf], AH[mf], BrL[nf]);
                    mma16(accim[mf][nf], AL[mf], BrH[nf]);
                }
        }
        __syncthreads();
    }

    // ---- epilogue: write tile + mirror (skip mirror on diagonal tiles) ----
#pragma unroll
    for (int mf = 0; mf < 4; mf++)
#pragma unroll
        for (int nf = 0; nf < 4; nf++) {
            unsigned r = row0 + wm * 64 + mf * 16 + gid;
            unsigned cc = col0 + wn * 32 + nf * 8 + 2 * tig;
            const float* cr = accre[mf][nf];
            const float* ci = accim[mf][nf];
            gA_re[(size_t)r * D + cc]           = cr[0];
            gA_re[(size_t)r * D + cc + 1]       = cr[1];
            gA_re[(size_t)(r + 8) * D + cc]     = cr[2];
            gA_re[(size_t)(r + 8) * D + cc + 1] = cr[3];
            gA_im[(size_t)r * D + cc]           = ci[0];
            gA_im[(size_t)r * D + cc + 1]       = ci[1];
            gA_im[(size_t)(r + 8) * D + cc]     = ci[2];
            gA_im[(size_t)(r + 8) * D + cc + 1] = ci[3];
            if (bi != bj) {
                gA_re[(size_t)cc * D + r]           = cr[0];
                gA_re[(size_t)(cc + 1) * D + r]     = cr[1];
                gA_re[(size_t)cc * D + r + 8]       = cr[2];
                gA_re[(size_t)(cc + 1) * D + r + 8] = cr[3];
                gA_im[(size_t)cc * D + r]           = -ci[0];
                gA_im[(size_t)(cc + 1) * D + r]     = -ci[1];
                gA_im[(size_t)cc * D + r + 8]       = -ci[2];
                gA_im[(size_t)(cc + 1) * D + r + 8] = -ci[3];
            }
        }
}

// ---------------------------------------------------------------------------
// trace: sum of re diagonal of rho -> 1/trace
// ---------------------------------------------------------------------------
__global__ void trace_kernel()
{
    __shared__ float red[256];
    float s = 0.f;
    for (int i = threadIdx.x; i < D; i += 256)
        s += gA_re[(size_t)i * D + i];
    red[threadIdx.x] = s;
    __syncthreads();
    for (int w = 128; w; w >>= 1) {
        if (threadIdx.x < w) red[threadIdx.x] += red[threadIdx.x + w];
        __syncthreads();
    }
    if (threadIdx.x == 0) g_inv_trace = 1.0f / red[0];
}

// ---------------------------------------------------------------------------
// Fused 2-qubit partial-trace sweep, factored into two 4-term complex stages.
//   out[(k,s1,s2), a, t] = sum M[s1,i1,j1] M[s2,i2,j2]
//                          * in[k, (2j1+j2)*rp + a, (2i1+i2)*cp + t]
// dir=0: A->B, dir=1: B->A. wim=0 skips imag store (last sweep).
// ---------------------------------------------------------------------------
__global__ void __launch_bounds__(256) qmt_sweep(int dir,
                                                 const float* __restrict__ Mr,
                                                 const float* __restrict__ Mi,
                                                 int lc, int wim)
{
    const float* __restrict__ in_re = dir ? gB_re : gA_re;
    const float* __restrict__ in_im = dir ? gB_im : gA_im;
    float* __restrict__ o_re = dir ? gA_re : gB_re;
    float* __restrict__ o_im = dir ? gA_im : gB_im;

    __shared__ float sr[16], si[16];   // M[s,i,j] at s*4+i*2+j
    int tid = threadIdx.x;
    if (tid < 16) { sr[tid] = Mr[tid]; si[tid] = Mi[tid]; }
    __syncthreads();

    unsigned gid = blockIdx.x * 256u + (unsigned)tid;   // 0 .. 2^20-1
    unsigned cp = 1u << lc;
    unsigned t = gid & (cp - 1u);
    unsigned a = (gid >> lc) & (cp - 1u);
    unsigned k = gid >> (2 * lc);
    unsigned base_in = k << (2 * lc + 4);

    float xr[16], xi[16];
#pragma unroll
    for (int J = 0; J < 4; J++)
#pragma unroll
        for (int I = 0; I < 4; I++) {
            unsigned off = base_in
                         + ((((unsigned)J << lc) + a) << (lc + 2))
                         + ((unsigned)I << lc) + t;
            xr[J * 4 + I] = in_re[off];
            xi[J * 4 + I] = in_im[off];
        }

    // stage 1: contract (j1,i1): y[s1][(j2,i2)]
    float yr[16], yi[16];
#pragma unroll
    for (int s1 = 0; s1 < 4; s1++)
#pragma unroll
        for (int j2 = 0; j2 < 2; j2++)
#pragma unroll
            for (int i2 = 0; i2 < 2; i2++) {
                float ar = 0.f, ai = 0.f;
#pragma unroll
                for (int j1 = 0; j1 < 2; j1++)
#pragma unroll
                    for (int i1 = 0; i1 < 2; i1++) {
                        float mr = sr[s1 * 4 + i1 * 2 + j1];
                        float mi = si[s1 * 4 + i1 * 2 + j1];
                        float vr = xr[(j1 * 2 + j2) * 4 + i1 * 2 + i2];
                        float vi = xi[(j1 * 2 + j2) * 4 + i1 * 2 + i2];
                        ar = fmaf(mr, vr, ar); ar = fmaf(-mi, vi, ar);
                        ai = fmaf(mr, vi, ai); ai = fmaf(mi, vr, ai);
                    }
                yr[s1 * 4 + j2 * 2 + i2] = ar;
                yi[s1 * 4 + j2 * 2 + i2] = ai;
            }

    // stage 2: contract (j2,i2)
#pragma unroll
    for (int s1 = 0; s1 < 4; s1++)
#pragma unroll
        for (int s2 = 0; s2 < 4; s2++) {
            float aR = 0.f, aI = 0.f;
#pragma unroll
            for (int j2 = 0; j2 < 2; j2++)
#pragma unroll
                for (int i2 = 0; i2 < 2; i2++) {
                    float mr = sr[s2 * 4 + i2 * 2 + j2];
                    float mi = si[s2 * 4 + i2 * 2 + j2];
                    float vr = yr[s1 * 4 + j2 * 2 + i2];
                    float vi = yi[s1 * 4 + j2 * 2 + i2];
                    aR = fmaf(mr, vr, aR); aR = fmaf(-mi, vi, aR);
                    aI = fmaf(mr, vi, aI); aI = fmaf(mi, vr, aI);
                }
            unsigned off = (((k << 4) + (unsigned)(s1 * 4 + s2)) << (2 * lc))
                         + (a << lc) + t;
            o_re[off] = aR;
            if (wim) o_im[off] = aI;
        }
}

// ---------------------------------------------------------------------------
// Gather: out[i] = P_all[idx[i]] / trace (real plane only; int32 indices).
// ---------------------------------------------------------------------------
__global__ void gather_kernel(const int* __restrict__ idx,
                              float* __restrict__ out, int n)
{
    int i = blockIdx.x * 256 + threadIdx.x;
    if (i < n) out[i] = gA_re[(unsigned)idx[i] & (NTOT - 1u)] * g_inv_trace;
}

// ---------------------------------------------------------------------------
extern "C" void kernel_launch(void* const* d_in, const int* in_sizes, int n_in,
                              void* d_out, int out_size)
{
    const float* params = (const float*)d_in[0];      // (2, 4096, 1024)
    const float* Mr = (const float*)d_in[1];          // (4,2,2)
    const float* Mi = (const float*)d_in[2];          // (4,2,2)
    const int* idx = (const int*)d_in[3];             // (1e6,) int32
    float* out = (float*)d_out;

    const float* Ur = params;
    const float* Ui = params + (size_t)D * RK;

    pack_split<<<16384, 256>>>(Ur, Ui);

    const int smem_bytes = 2 * 8 * 128 * PITB;        // 163840
    cudaFuncSetAttribute(gemm_mma,
                         cudaFuncAttributeMaxDynamicSharedMemorySize, smem_bytes);
    gemm_mma<<<528, 256, smem_bytes>>>();

    trace_kernel<<<1, 256>>>();

    int dir = 0;
    for (int n = 1; n <= 6; n++) {
        qmt_sweep<<<4096, 256>>>(dir, Mr, Mi, 12 - 2 * n, n < 6 ? 1 : 0);
        dir ^= 1;
    }
    // final result (real plane) in gA_re

    int nq = in_sizes[3];
    gather_kernel<<<(nq + 255) / 256, 256>>>(idx, out, nq);
}